// round 13
// baseline (speedup 1.0000x reference)
#include <cuda_runtime.h>
#include <cstdint>

#define TH 1.0f
#define EPS_BN 1e-5f

// scratch (no allocations allowed -> device globals)
__device__ float g_dm[256 * 256];
__device__ int   g_rowok[256];
__device__ int   g_done = 0;       // dm-row completion counter (reset each run)
__device__ int   g_ready = 0;      // gate: dist image 0 fully written
__device__ int   g_repl_done = 0;  // replication completion counter

__device__ __forceinline__ uint32_t smem_u32(const void* p) {
    uint32_t a;
    asm("{ .reg .u64 t; cvta.to.shared.u64 t, %1; cvt.u32.u64 %0, t; }"
        : "=r"(a) : "l"(p));
    return a;
}
__device__ __forceinline__ void mbar_init(uint32_t mb) {
    asm volatile("mbarrier.init.shared.b64 [%0], 1;" :: "r"(mb) : "memory");
}
__device__ __forceinline__ void g2s(uint32_t sdst, const void* gsrc,
                                    uint32_t bytes, uint32_t mb) {
    asm volatile("mbarrier.arrive.expect_tx.shared.b64 _, [%0], %1;"
                 :: "r"(mb), "r"(bytes) : "memory");
    asm volatile(
        "cp.async.bulk.shared::cluster.global.mbarrier::complete_tx::bytes "
        "[%0], [%1], %2, [%3];"
        :: "r"(sdst), "l"(gsrc), "r"(bytes), "r"(mb) : "memory");
}
__device__ __forceinline__ void mbar_wait0(uint32_t mb) {
    uint32_t done = 0;
    while (!done) {
        asm volatile(
            "{\n\t.reg .pred p;\n\t"
            "mbarrier.try_wait.parity.shared.b64 p, [%1], 0;\n\t"
            "selp.u32 %0, 1, 0, p;\n\t}"
            : "=r"(done) : "r"(mb) : "memory");
    }
}
__device__ __forceinline__ void s2g(void* gdst, uint32_t ssrc, uint32_t bytes) {
    asm volatile("cp.async.bulk.global.shared::cta.bulk_group [%0], [%1], %2;"
                 :: "l"(gdst), "r"(ssrc), "r"(bytes) : "memory");
}

// ---------------------------------------------------------------------------
// Single fused kernel, 896 blocks x 256 threads, 66.5KB dynamic smem:
//  b in [0,256)   : dm row n=b. Thread m -> dm[n][m]; plain stores to g_dm and
//                   dist image t=0. Done-counter; 256th block releases g_ready
//                   and computes group_indices (fast path all-zeros; exact
//                   lax.scan replica fallback).
//  b in [256,768) : TMA copy v -> v_grouped: 4x16KB G2S in flight, then 4 S2G.
//  b in [768,896) : gate on g_ready; G2S one 32KB chunk (p=idx&7) of image 0,
//                   S2G to 8 t-copies (t = (idx>>3)*8 + j, skipping t=0).
//                   Last repl block resets the gate for graph replay.
// ---------------------------------------------------------------------------
__global__ void fused_kernel(const float* __restrict__ v,
                             const float* __restrict__ w1,
                             const float* __restrict__ b1,
                             const float* __restrict__ bn_gamma,
                             const float* __restrict__ bn_beta,
                             const float* __restrict__ bn_mean,
                             const float* __restrict__ bn_var,
                             const float* __restrict__ w2,
                             const float* __restrict__ b2,
                             float* __restrict__ out) {
    extern __shared__ char dyn_raw[];
    char* buf = (char*)(((uintptr_t)dyn_raw + 1023) & ~(uintptr_t)1023);
    __shared__ __align__(8) unsigned long long mbar[4];
    int b = blockIdx.x;
    int tid = threadIdx.x;
    const long DIST_B = 33555456L;          // byte offset of dist_mat_full

    if (b >= 768) {
        // ---- replication blocks: dist image 0 -> images 1..127 ----
        if (tid == 0) {
            while (atomicAdd(&g_ready, 0) == 0) __nanosleep(64);
            __threadfence();
            asm volatile("fence.proxy.async;" ::: "memory");
            int idx = b - 768;
            int p = idx & 7;                // 32KB chunk of the 256KB image
            int g = idx >> 3;               // t-group (8 t's each)
            uint32_t mb = smem_u32(&mbar[0]);
            uint32_t sb = smem_u32(buf);
            mbar_init(mb);
            asm volatile("fence.proxy.async.shared::cta;" ::: "memory");
            const char* src = (const char*)out + DIST_B + (long)p * 32768;
            g2s(sb, src, 32768u, mb);
            mbar_wait0(mb);
            #pragma unroll
            for (int j = 0; j < 8; j++) {
                int t = g * 8 + j;
                if (t == 0) continue;       // image 0 already written by dm
                char* dst = (char*)out + DIST_B + (long)t * 262144 + (long)p * 32768;
                s2g(dst, sb, 32768u);
            }
            asm volatile("cp.async.bulk.commit_group;" ::: "memory");
            asm volatile("cp.async.bulk.wait_group 0;" ::: "memory");
            int old = atomicAdd(&g_repl_done, 1);
            if (old == 127) { g_repl_done = 0; atomicExch(&g_ready, 0); }
        }
        return;
    }

    if (b >= 256) {
        // ---- copy blocks: v_grouped = v_rel, 64KB per block via TMA ----
        if (tid == 0) {
            int idx = b - 256;
            const char* src = (const char*)v + (long)idx * 65536;
            char* dst = (char*)out + (long)idx * 65536;
            uint32_t sb = smem_u32(buf);
            #pragma unroll
            for (int i = 0; i < 4; i++) mbar_init(smem_u32(&mbar[i]));
            asm volatile("fence.proxy.async.shared::cta;" ::: "memory");
            #pragma unroll
            for (int i = 0; i < 4; i++)
                g2s(sb + i * 16384, src + (long)i * 16384, 16384u,
                    smem_u32(&mbar[i]));
            #pragma unroll
            for (int i = 0; i < 4; i++) {
                mbar_wait0(smem_u32(&mbar[i]));
                s2g(dst + (long)i * 16384, sb + i * 16384, 16384u);
            }
            asm volatile("cp.async.bulk.commit_group;" ::: "memory");
            asm volatile("cp.async.bulk.wait_group 0;" ::: "memory");
        }
        return;
    }

    // ---- dm blocks ----
    __shared__ float sa[32], sw0[32], sw1[32], sb_[32];
    __shared__ float sK;
    __shared__ int s_islast;
    if (tid < 32) {
        float scale = bn_gamma[tid] * rsqrtf(bn_var[tid] + EPS_BN);
        float w2o = w2[tid];
        sa[tid]  = w2o * scale;
        sw0[tid] = w1[tid * 2 + 0];
        sw1[tid] = w1[tid * 2 + 1];
        sb_[tid] = b1[tid];
        float kpart = w2o * (bn_beta[tid] - bn_mean[tid] * scale);
        #pragma unroll
        for (int off = 16; off > 0; off >>= 1)
            kpart += __shfl_down_sync(0xffffffffu, kpart, off);
        if (tid == 0) sK = kpart + b2[0];
    }
    __syncthreads();

    int n = b;
    int m = tid;
    // x[c][i] = v_rel[0, c, 127, i], layout (1,256,128,256)
    const int base = 127 * 256;
    float d0 = v[base + n] - v[base + m];
    float d1 = v[32768 + base + n] - v[32768 + base + m];

    float sp = sK, sn = sK;
    #pragma unroll
    for (int o = 0; o < 32; o++) {
        float lin = sw0[o] * d0 + sw1[o] * d1;
        sp += sa[o] * fmaxf(lin + sb_[o], 0.0f);
        sn += sa[o] * fmaxf(sb_[o] - lin, 0.0f);
    }
    float val = 0.5f * (expf(sp) + expf(sn));
    g_dm[n * 256 + m] = val;
    out[8388864 + n * 256 + m] = val;       // dist image t=0

    int anyok = __syncthreads_or((m < n) && (val <= TH));
    if (tid == 0) {
        g_rowok[n] = anyok;
        __threadfence();                    // commit row + image0 + rowok
        int old = atomicAdd(&g_done, 1);
        s_islast = (old == 255);
    }
    __syncthreads();
    if (!s_islast) return;
    __threadfence();                        // see all rows' writes
    if (tid == 0) atomicExch(&g_ready, 1);  // release replication blocks

    float* __restrict__ out_gi = out + 8388608;
    int rowok = g_rowok[tid];
    bool fast = __syncthreads_and(tid == 0 || rowok);
    if (fast) {
        // every row r>=1 merges into the component labeled 0 -> all ranks 0
        out_gi[tid] = 0.0f;
    } else {
        // ---- exact fallback: row-parallel replica of reference lax.scan ----
        __shared__ int comp[256];
        __shared__ int firstidx[256];
        __shared__ int marked[256];
        __shared__ int cstar;
        __shared__ int newcomp;
        comp[tid] = tid;
        __syncthreads();

        for (int r = 1; r < 256; r++) {
            firstidx[tid] = 0x7fffffff;
            marked[tid] = 0;
            if (tid == 0) cstar = -1;
            __syncthreads();

            int myc = comp[tid];
            int rcomp = comp[r];
            bool okc = (tid < r) && (g_dm[r * 256 + tid] <= TH);
            if (okc) {
                atomicMin(&firstidx[myc], tid);
                marked[myc] = 1;
            }
            if (tid == r) marked[myc] = 1;
            __syncthreads();

            if (okc && myc != rcomp && firstidx[myc] == tid)
                atomicMax(&cstar, tid);
            __syncthreads();

            int cs = cstar;
            if (cs >= 0 && tid == cs) newcomp = myc;
            __syncthreads();
            if (cs >= 0 && marked[myc]) comp[tid] = newcomp;
            __syncthreads();
        }

        __shared__ int pres[256];
        pres[tid] = 0;
        __syncthreads();
        pres[comp[tid]] = 1;
        __syncthreads();
        for (int off = 1; off < 256; off <<= 1) {
            int t = (tid >= off) ? pres[tid - off] : 0;
            __syncthreads();
            pres[tid] += t;
            __syncthreads();
        }
        out_gi[tid] = (float)(pres[comp[tid]] - 1);
    }
    __syncthreads();
    if (tid == 0) g_done = 0;               // reset for next graph replay
}

extern "C" void kernel_launch(void* const* d_in, const int* in_sizes, int n_in,
                              void* d_out, int out_size) {
    const float* v_rel    = (const float*)d_in[0];
    const float* w1       = (const float*)d_in[1];
    const float* b1       = (const float*)d_in[2];
    const float* bn_gamma = (const float*)d_in[3];
    const float* bn_beta  = (const float*)d_in[4];
    const float* bn_mean  = (const float*)d_in[5];
    const float* bn_var   = (const float*)d_in[6];
    const float* w2       = (const float*)d_in[7];
    const float* b2       = (const float*)d_in[8];
    float* out = (float*)d_out;

    static int attr_set = 0;
    if (!attr_set) {
        cudaFuncSetAttribute(fused_kernel,
                             cudaFuncAttributeMaxDynamicSharedMemorySize, 66560);
        attr_set = 1;
    }
    fused_kernel<<<896, 256, 66560>>>(v_rel, w1, b1, bn_gamma, bn_beta,
                                      bn_mean, bn_var, w2, b2, out);
}